// round 1
// baseline (speedup 1.0000x reference)
#include <cuda_runtime.h>
#include <math.h>

#define TT   8192      // tokens
#define DD   2048      // model dim
#define FF   1024      // ffn dim
#define EE   7         // routed experts
#define CAPX 1170      // capacity = floor(8192/7)

// ---------------- scratch (device globals: allocation-free) ----------------
__device__ int   g_top[TT * 2];          // per-token top-2 expert ids
__device__ float g_affv[TT * 2];         // per-token top-2 affinities
__device__ int   g_sel_tok[EE * CAPX];   // per-expert selected token ids
__device__ float g_sel_w[EE * CAPX];     // per-expert weights (0 = padded slot)
__device__ float g_H2[(size_t)TT * 2 * FF];  // GEMM1 raw output  [rows, 2F]
__device__ float g_Hs[(size_t)TT * FF];      // swiglu output     [rows, F]

// ---------------- gating: logits -> sigmoid -> top-2 ----------------
__global__ void gating_kernel(const float* __restrict__ x,
                              const float* __restrict__ gw,
                              const float* __restrict__ bias) {
    int t = blockIdx.x;
    const float* xr = x + (size_t)t * DD;
    float s[EE];
#pragma unroll
    for (int e = 0; e < EE; e++) s[e] = 0.f;
    for (int d = threadIdx.x; d < DD; d += 256) {
        float xv = xr[d];
#pragma unroll
        for (int e = 0; e < EE; e++) s[e] = fmaf(xv, gw[d * EE + e], s[e]);
    }
#pragma unroll
    for (int off = 16; off > 0; off >>= 1) {
#pragma unroll
        for (int e = 0; e < EE; e++)
            s[e] += __shfl_down_sync(0xffffffffu, s[e], off);
    }
    __shared__ float red[8][EE];
    int warp = threadIdx.x >> 5, lane = threadIdx.x & 31;
    if (lane == 0) {
#pragma unroll
        for (int e = 0; e < EE; e++) red[warp][e] = s[e];
    }
    __syncthreads();
    if (threadIdx.x == 0) {
        float aff[EE];
#pragma unroll
        for (int e = 0; e < EE; e++) {
            float v = 0.f;
            for (int w = 0; w < 8; w++) v += red[w][e];
            v += bias[e];
            aff[e] = 1.f / (1.f + expf(-v));
        }
        // top-2 with lowest-index tie-break (matches jax.lax.top_k)
        int e0 = 0;
        for (int e = 1; e < EE; e++) if (aff[e] > aff[e0]) e0 = e;
        int e1 = -1;
        for (int e = 0; e < EE; e++) {
            if (e == e0) continue;
            if (e1 < 0 || aff[e] > aff[e1]) e1 = e;
        }
        g_top[2 * t] = e0;  g_top[2 * t + 1] = e1;
        g_affv[2 * t] = aff[e0];  g_affv[2 * t + 1] = aff[e1];
    }
}

// ---------------- per-expert capacity selection (exact top-CAP) ----------------
// One block per expert: bitonic sort of 8192 keys (ascending ~aff_bits, then
// ascending token id) == descending affinity with lowest-index tie-break.
__global__ void select_kernel() {
    int e = blockIdx.x;
    __shared__ unsigned int   skey[TT];   // 32 KB
    __shared__ unsigned short stok[TT];   // 16 KB  (total = 48 KB static)
    for (int t = threadIdx.x; t < TT; t += blockDim.x) {
        unsigned int key = 0xFFFFFFFFu;  // sentinel: not a candidate
        if (g_top[2 * t] == e)          key = ~__float_as_uint(g_affv[2 * t]);
        else if (g_top[2 * t + 1] == e) key = ~__float_as_uint(g_affv[2 * t + 1]);
        skey[t] = key;
        stok[t] = (unsigned short)t;
    }
    __syncthreads();
    for (int k = 2; k <= TT; k <<= 1) {
        for (int j = k >> 1; j > 0; j >>= 1) {
            for (int i = threadIdx.x; i < TT; i += blockDim.x) {
                int l = i ^ j;
                if (l > i) {
                    bool up = ((i & k) == 0);
                    unsigned int   ki = skey[i], kl = skey[l];
                    unsigned short ti = stok[i], tl = stok[l];
                    bool gt = (ki > kl) || (ki == kl && ti > tl);
                    if (gt == up) {
                        skey[i] = kl; skey[l] = ki;
                        stok[i] = tl; stok[l] = ti;
                    }
                }
            }
            __syncthreads();
        }
    }
    for (int i = threadIdx.x; i < CAPX; i += blockDim.x) {
        unsigned int key = skey[i];
        if (key != 0xFFFFFFFFu) {
            g_sel_tok[e * CAPX + i] = (int)stok[i];
            g_sel_w[e * CAPX + i]   = __uint_as_float(~key);
        } else {
            g_sel_tok[e * CAPX + i] = 0;
            g_sel_w[e * CAPX + i]   = 0.f;   // padded slot: contributes nothing
        }
    }
}

// ---------------- SwiGLU: g_Hs[m,f] = h1 * silu(h2) ----------------
__global__ void swiglu_kernel(int rows) {
    size_t i = (size_t)blockIdx.x * blockDim.x + threadIdx.x;
    size_t total = (size_t)rows * FF;
    if (i >= total) return;
    size_t m = i / FF, f = i % FF;
    float a = g_H2[m * (2 * FF) + f];
    float b = g_H2[m * (2 * FF) + FF + f];
    g_Hs[i] = a * (b / (1.f + expf(-b)));
}

// ---------------- tiled fp32 GEMM: C[M,N] = A[M,K] @ B[K,N] ----------------
// GATHER: A rows indexed through rin (token gather). SCATTER: weighted
// atomicAdd of C rows into out[token] (routed combine).
template <bool GATHER, bool SCATTER>
__global__ void __launch_bounds__(256)
sgemm_kernel(const float* __restrict__ A, const float* __restrict__ Bm,
             float* __restrict__ C, int M, int N, int K,
             size_t Az, size_t Bz, size_t Cz,
             const int* __restrict__ rin, int rinz,
             const int* __restrict__ rout, const float* __restrict__ wout,
             int routz) {
    constexpr int BM = 128, BN = 128, BK = 16;
    int z = blockIdx.z;
    const float* Ab = A + (size_t)z * Az;
    const float* Bb = Bm + (size_t)z * Bz;
    float* Cb = C + (size_t)z * Cz;

    __shared__ float As[BK][BM];
    __shared__ float Bs[BK][BN];

    int tid = threadIdx.x;
    int blockRow = blockIdx.y * BM;
    int blockCol = blockIdx.x * BN;

    int arow = tid >> 2;            // 0..63
    int acol = (tid & 3) << 2;      // 0,4,8,12
    int brow = tid >> 5;            // 0..7
    int bcol = (tid & 31) << 2;     // 0..124

    const float* aptr[2];
    bool avalid[2];
#pragma unroll
    for (int r = 0; r < 2; r++) {
        int m = blockRow + arow + r * 64;
        avalid[r] = (m < M);
        int row = avalid[r] ? m : 0;
        if (GATHER) row = rin[(size_t)z * rinz + row];
        aptr[r] = Ab + (size_t)row * K;
    }

    float acc[8][8];
#pragma unroll
    for (int i = 0; i < 8; i++)
#pragma unroll
        for (int j = 0; j < 8; j++) acc[i][j] = 0.f;

    int ty = tid >> 4;   // 0..15
    int tx = tid & 15;   // 0..15

    for (int kt = 0; kt < K; kt += BK) {
#pragma unroll
        for (int r = 0; r < 2; r++) {
            float4 v = make_float4(0.f, 0.f, 0.f, 0.f);
            if (avalid[r]) v = *(const float4*)(aptr[r] + kt + acol);
            As[acol + 0][arow + r * 64] = v.x;
            As[acol + 1][arow + r * 64] = v.y;
            As[acol + 2][arow + r * 64] = v.z;
            As[acol + 3][arow + r * 64] = v.w;
        }
#pragma unroll
        for (int r = 0; r < 2; r++) {
            float4 v = *(const float4*)(Bb + (size_t)(kt + brow + r * 8) * N +
                                        blockCol + bcol);
            *(float4*)&Bs[brow + r * 8][bcol] = v;
        }
        __syncthreads();
#pragma unroll
        for (int kk = 0; kk < BK; kk++) {
            float a[8], b[8];
#pragma unroll
            for (int i = 0; i < 8; i++) a[i] = As[kk][ty * 8 + i];
#pragma unroll
            for (int j = 0; j < 8; j++) b[j] = Bs[kk][tx * 8 + j];
#pragma unroll
            for (int i = 0; i < 8; i++)
#pragma unroll
                for (int j = 0; j < 8; j++)
                    acc[i][j] = fmaf(a[i], b[j], acc[i][j]);
        }
        __syncthreads();
    }

    int crow0 = blockRow + ty * 8;
    int ccol0 = blockCol + tx * 8;
    if (!SCATTER) {
#pragma unroll
        for (int i = 0; i < 8; i++) {
            int m = crow0 + i;
            if (m >= M) break;
            float4 v0 = make_float4(acc[i][0], acc[i][1], acc[i][2], acc[i][3]);
            float4 v1 = make_float4(acc[i][4], acc[i][5], acc[i][6], acc[i][7]);
            *(float4*)(Cb + (size_t)m * N + ccol0) = v0;
            *(float4*)(Cb + (size_t)m * N + ccol0 + 4) = v1;
        }
    } else {
#pragma unroll
        for (int i = 0; i < 8; i++) {
            int m = crow0 + i;
            if (m >= M) break;
            float wm = wout[(size_t)z * routz + m];
            if (wm == 0.f) continue;
            int tok = rout[(size_t)z * routz + m];
            float* cp = Cb + (size_t)tok * N + ccol0;
#pragma unroll
            for (int j = 0; j < 8; j++) atomicAdd(cp + j, wm * acc[i][j]);
        }
    }
}

// ---------------- launch ----------------
extern "C" void kernel_launch(void* const* d_in, const int* in_sizes, int n_in,
                              void* d_out, int out_size) {
    const float* x   = (const float*)d_in[0];
    const float* gw  = (const float*)d_in[1];
    const float* eb  = (const float*)d_in[2];
    const float* sw1 = (const float*)d_in[3];
    const float* sw2 = (const float*)d_in[4];
    const float* rw1 = (const float*)d_in[5];
    const float* rw2 = (const float*)d_in[6];
    float* out = (float*)d_out;

    float *H2, *Hs, *selw;
    int* seltok;
    cudaGetSymbolAddress((void**)&H2, g_H2);
    cudaGetSymbolAddress((void**)&Hs, g_Hs);
    cudaGetSymbolAddress((void**)&seltok, g_sel_tok);
    cudaGetSymbolAddress((void**)&selw, g_sel_w);

    // 1) gating + 2) capacity selection
    gating_kernel<<<TT, 256>>>(x, gw, eb);
    select_kernel<<<EE, 1024>>>();

    // 3) shared expert: H2 = X @ W1 ; Hs = swiglu(H2) ; out = Hs @ W2
    sgemm_kernel<false, false><<<dim3(2 * FF / 128, TT / 128, 1), 256>>>(
        x, sw1, H2, TT, 2 * FF, DD, 0, 0, 0, nullptr, 0, nullptr, nullptr, 0);
    {
        size_t total = (size_t)TT * FF;
        swiglu_kernel<<<(unsigned)((total + 255) / 256), 256>>>(TT);
    }
    sgemm_kernel<false, false><<<dim3(DD / 128, TT / 128, 1), 256>>>(
        Hs, sw2, out, TT, DD, FF, 0, 0, 0, nullptr, 0, nullptr, nullptr, 0);

    // 4) routed experts: gather -> GEMM1 -> swiglu -> GEMM2 -> weighted scatter-add
    sgemm_kernel<true, false><<<dim3(2 * FF / 128, (CAPX + 127) / 128, EE), 256>>>(
        x, rw1, H2, CAPX, 2 * FF, DD,
        0, (size_t)DD * 2 * FF, (size_t)CAPX * 2 * FF,
        seltok, CAPX, nullptr, nullptr, 0);
    {
        size_t total = (size_t)EE * CAPX * FF;
        swiglu_kernel<<<(unsigned)((total + 255) / 256), 256>>>(EE * CAPX);
    }
    sgemm_kernel<false, true><<<dim3(DD / 128, (CAPX + 127) / 128, EE), 256>>>(
        Hs, rw2, out, CAPX, DD, FF,
        (size_t)CAPX * FF, (size_t)FF * DD, 0,
        nullptr, 0, seltok, selw, CAPX);
}

// round 3
// speedup vs baseline: 6.0841x; 6.0841x over previous
#include <cuda_runtime.h>
#include <cuda_fp16.h>
#include <math.h>
#include <stdint.h>

#define TT   8192
#define DD   2048
#define FF   1024
#define EE   7
#define CAPX 1170
#define MPAD 1280
#define NST  3
#define STAGE_BYTES 32768           // A 16KB + B 16KB (fp16, 128x64 each)
#define SMEM_BYTES (NST * STAGE_BYTES)

// ---------------- scratch (device globals) ----------------
__device__ int    g_top[TT * 2];
__device__ float  g_affv[TT * 2];
__device__ int    g_sel_tok[EE * CAPX];
__device__ float  g_sel_w[EE * CAPX];
__device__ __half g_Xr[(size_t)TT * DD];
__device__ __half g_Xg[(size_t)EE * MPAD * DD];
__device__ float  g_H2[(size_t)EE * MPAD * 2 * FF];
__device__ __half g_Hs[(size_t)EE * MPAD * FF];
__device__ __half g_sw1T[(size_t)2 * FF * DD];
__device__ __half g_sw2T[(size_t)DD * FF];
__device__ __half g_rw1T[(size_t)EE * 2 * FF * DD];
__device__ __half g_rw2T[(size_t)EE * DD * FF];

// ---------------- helpers ----------------
__device__ __forceinline__ uint32_t smem_u32(const void* p) {
    uint32_t a;
    asm("{ .reg .u64 t; cvta.to.shared.u64 t, %1; cvt.u32.u64 %0, t; }" : "=r"(a) : "l"(p));
    return a;
}
__device__ __forceinline__ void cp16(uint32_t d, const void* s) {
    asm volatile("cp.async.cg.shared.global [%0], [%1], 16;" :: "r"(d), "l"(s));
}
#define CP_COMMIT() asm volatile("cp.async.commit_group;" ::: "memory")
#define CP_WAIT1()  asm volatile("cp.async.wait_group 1;" ::: "memory")
#define SWZ(o) ((o) ^ (((o) >> 3) & 0x70))

__device__ __forceinline__ void ldsm4(uint32_t* r, uint32_t addr) {
    asm volatile("ldmatrix.sync.aligned.m8n8.x4.shared.b16 {%0,%1,%2,%3}, [%4];"
                 : "=r"(r[0]), "=r"(r[1]), "=r"(r[2]), "=r"(r[3]) : "r"(addr));
}
__device__ __forceinline__ void mma16816(float* d, const uint32_t* a,
                                         const uint32_t* b) {
    asm volatile(
        "mma.sync.aligned.m16n8k16.row.col.f32.f16.f16.f32 "
        "{%0,%1,%2,%3}, {%4,%5,%6,%7}, {%8,%9}, {%0,%1,%2,%3};"
        : "+f"(d[0]), "+f"(d[1]), "+f"(d[2]), "+f"(d[3])
        : "r"(a[0]), "r"(a[1]), "r"(a[2]), "r"(a[3]), "r"(b[0]), "r"(b[1]));
}

// ---------------- gating (exact fp32) ----------------
__global__ void gating_kernel(const float* __restrict__ x,
                              const float* __restrict__ gw,
                              const float* __restrict__ bias) {
    int t = blockIdx.x;
    const float* xr = x + (size_t)t * DD;
    float s[EE];
#pragma unroll
    for (int e = 0; e < EE; e++) s[e] = 0.f;
    for (int d = threadIdx.x; d < DD; d += 256) {
        float xv = xr[d];
#pragma unroll
        for (int e = 0; e < EE; e++) s[e] = fmaf(xv, gw[d * EE + e], s[e]);
    }
#pragma unroll
    for (int off = 16; off > 0; off >>= 1)
#pragma unroll
        for (int e = 0; e < EE; e++)
            s[e] += __shfl_down_sync(0xffffffffu, s[e], off);
    __shared__ float red[8][EE];
    int warp = threadIdx.x >> 5, lane = threadIdx.x & 31;
    if (lane == 0)
#pragma unroll
        for (int e = 0; e < EE; e++) red[warp][e] = s[e];
    __syncthreads();
    if (threadIdx.x == 0) {
        float aff[EE];
#pragma unroll
        for (int e = 0; e < EE; e++) {
            float v = 0.f;
            for (int w = 0; w < 8; w++) v += red[w][e];
            v += bias[e];
            aff[e] = 1.f / (1.f + expf(-v));
        }
        int e0 = 0;
        for (int e = 1; e < EE; e++) if (aff[e] > aff[e0]) e0 = e;
        int e1 = -1;
        for (int e = 0; e < EE; e++) {
            if (e == e0) continue;
            if (e1 < 0 || aff[e] > aff[e1]) e1 = e;
        }
        g_top[2 * t] = e0;  g_top[2 * t + 1] = e1;
        g_affv[2 * t] = aff[e0];  g_affv[2 * t + 1] = aff[e1];
    }
}

// ---------------- per-expert capacity selection (exact top-CAP) ----------------
__global__ void select_kernel() {
    int e = blockIdx.x;
    __shared__ unsigned int   skey[TT];
    __shared__ unsigned short stok[TT];
    for (int t = threadIdx.x; t < TT; t += blockDim.x) {
        unsigned int key = 0xFFFFFFFFu;
        if (g_top[2 * t] == e)          key = ~__float_as_uint(g_affv[2 * t]);
        else if (g_top[2 * t + 1] == e) key = ~__float_as_uint(g_affv[2 * t + 1]);
        skey[t] = key;
        stok[t] = (unsigned short)t;
    }
    __syncthreads();
    for (int k = 2; k <= TT; k <<= 1) {
        for (int j = k >> 1; j > 0; j >>= 1) {
            for (int i = threadIdx.x; i < TT; i += blockDim.x) {
                int l = i ^ j;
                if (l > i) {
                    bool up = ((i & k) == 0);
                    unsigned int   ki = skey[i], kl = skey[l];
                    unsigned short ti = stok[i], tl = stok[l];
                    bool gt = (ki > kl) || (ki == kl && ti > tl);
                    if (gt == up) {
                        skey[i] = kl; skey[l] = ki;
                        stok[i] = tl; stok[l] = ti;
                    }
                }
            }
            __syncthreads();
        }
    }
    for (int i = threadIdx.x; i < CAPX; i += blockDim.x) {
        unsigned int key = skey[i];
        if (key != 0xFFFFFFFFu) {
            g_sel_tok[e * CAPX + i] = (int)stok[i];
            g_sel_w[e * CAPX + i]   = __uint_as_float(~key);
        } else {
            g_sel_tok[e * CAPX + i] = 0;
            g_sel_w[e * CAPX + i]   = 0.f;
        }
    }
}

// ---------------- prep: x -> fp16 ----------------
__global__ void roundx_kernel(const float* __restrict__ x) {
    size_t i = (size_t)blockIdx.x * blockDim.x + threadIdx.x;
    float4 v = ((const float4*)x)[i];
    __half2 h0 = __floats2half2_rn(v.x, v.y);
    __half2 h1 = __floats2half2_rn(v.z, v.w);
    ((uint2*)g_Xr)[i] = make_uint2(*(uint32_t*)&h0, *(uint32_t*)&h1);
}

// ---------------- prep: transpose [z][K][N] fp32 -> [z][N][K] fp16 ----------------
__global__ void transpose_kernel(const float* __restrict__ in, __half* __restrict__ out,
                                 int K, int N) {
    __shared__ float t[32][33];
    int z = blockIdx.z;
    in  += (size_t)z * K * N;
    out += (size_t)z * N * K;
    int n0 = blockIdx.x * 32, k0 = blockIdx.y * 32;
    int tx = threadIdx.x, ty = threadIdx.y;
#pragma unroll
    for (int i = 0; i < 32; i += 8)
        t[ty + i][tx] = in[(size_t)(k0 + ty + i) * N + n0 + tx];
    __syncthreads();
#pragma unroll
    for (int i = 0; i < 32; i += 8)
        out[(size_t)(n0 + ty + i) * K + k0 + tx] = __float2half_rn(t[tx][ty + i]);
}

// ---------------- gather routed tokens -> fp16 ----------------
__global__ void gather_kernel(const float* __restrict__ x) {
    int r = blockIdx.x;
    int z = r / MPAD, i = r - z * MPAD;
    int tok = (i < CAPX) ? g_sel_tok[z * CAPX + i] : 0;
    const float4* src = (const float4*)(x + (size_t)tok * DD);
    uint2* dst = (uint2*)(g_Xg + (size_t)r * DD);
    for (int c = threadIdx.x; c < DD / 4; c += blockDim.x) {
        float4 v = src[c];
        __half2 h0 = __floats2half2_rn(v.x, v.y);
        __half2 h1 = __floats2half2_rn(v.z, v.w);
        dst[c] = make_uint2(*(uint32_t*)&h0, *(uint32_t*)&h1);
    }
}

// ---------------- SwiGLU: fp32 H2 -> fp16 Hs ----------------
__global__ void swiglu_kernel(int rows) {
    int idx = blockIdx.x * blockDim.x + threadIdx.x;
    int m = idx >> 8;            // 256 float4 per 1024-wide half-row
    int f4 = idx & 255;
    if (m >= rows) return;
    const float4* h = (const float4*)(g_H2 + (size_t)m * 2 * FF);
    float4 a = h[f4], b = h[256 + f4];
    float o0 = a.x * (b.x / (1.f + expf(-b.x)));
    float o1 = a.y * (b.y / (1.f + expf(-b.y)));
    float o2 = a.z * (b.z / (1.f + expf(-b.z)));
    float o3 = a.w * (b.w / (1.f + expf(-b.w)));
    __half2 h0 = __floats2half2_rn(o0, o1);
    __half2 h1 = __floats2half2_rn(o2, o3);
    ((uint2*)(g_Hs + (size_t)m * FF))[f4] = make_uint2(*(uint32_t*)&h0, *(uint32_t*)&h1);
}

// ---------------- fp16 mma.sync GEMM: C[M,2048] = A[M,K] @ B[2048,K]^T ----------------
// BM=128 BN=128 BK=64, 256 thr (8 warps, 64x32 warp tiles), 3-stage cp.async.
template <bool SCATTER>
__global__ void __launch_bounds__(256)
gemm_kernel(const __half* __restrict__ A, const __half* __restrict__ B,
            float* __restrict__ C, int K, size_t Az, size_t Bz, size_t Cz,
            const int* __restrict__ rout, const float* __restrict__ wout, int routz) {
    extern __shared__ char smem[];
    const uint32_t sb = smem_u32(smem);
    const int tid = threadIdx.x;
    const int lane = tid & 31, wid = tid >> 5;
    const int wm = (wid & 1) * 64;          // warp M offset in tile
    const int wn = (wid >> 1) * 32;         // warp N offset in tile
    const int z = blockIdx.z;

    const __half* Ab = A + (size_t)z * Az + (size_t)blockIdx.y * 128 * K;
    const __half* Bb = B + (size_t)z * Bz + (size_t)blockIdx.x * 128 * K;

    const int kIters = K >> 6;

    // cp.async layout: thread t covers chunks t+j*256 (chunk = 16B of a 128B row)
    const int lrow = tid >> 3;      // 0..31 base row
    const int lc   = tid & 7;       // 16B chunk within row

    auto load_stage = [&](int s, int kt) {
        uint32_t abase = sb + s * STAGE_BYTES;
        uint32_t bbase = abase + 16384;
        const __half* ap = Ab + kt * 64 + lc * 8;
        const __half* bp = Bb + kt * 64 + lc * 8;
#pragma unroll
        for (int j = 0; j < 4; j++) {
            int r = lrow + j * 32;
            cp16(abase + SWZ(r * 128 + lc * 16), ap + (size_t)r * K);
        }
#pragma unroll
        for (int j = 0; j < 4; j++) {
            int r = lrow + j * 32;
            cp16(bbase + SWZ(r * 128 + lc * 16), bp + (size_t)r * K);
        }
    };

    float acc[4][4][4];
#pragma unroll
    for (int i = 0; i < 4; i++)
#pragma unroll
        for (int j = 0; j < 4; j++)
#pragma unroll
            for (int q = 0; q < 4; q++) acc[i][j][q] = 0.f;

    load_stage(0, 0); CP_COMMIT();
    load_stage(1, 1); CP_COMMIT();

    const int g  = lane >> 3;       // ldmatrix address group
    const int l7 = lane & 7;
    // A frag rows: wm + mi*16 + (g&1)*8 + l7 ; col byte: ks*32 + (g>>1)*16
    // B frag rows: wn + p*16 + (g>>1)*8 + l7 ; col byte: ks*32 + (g&1)*16
    const int arow = wm + (g & 1) * 8 + l7;
    const int brow = wn + (g >> 1) * 8 + l7;
    const int acb  = (g >> 1) * 16;
    const int bcb  = (g & 1) * 16;

    for (int kt = 0; kt < kIters; kt++) {
        int s = kt % NST;
        CP_WAIT1();
        __syncthreads();
        if (kt + 2 < kIters) load_stage((kt + 2) % NST, kt + 2);
        CP_COMMIT();

        uint32_t abase = sb + s * STAGE_BYTES;
        uint32_t bbase = abase + 16384;
#pragma unroll
        for (int ks = 0; ks < 4; ks++) {
            uint32_t af[4][4], bf[2][4];
#pragma unroll
            for (int mi = 0; mi < 4; mi++)
                ldsm4(af[mi], abase + SWZ((arow + mi * 16) * 128 + ks * 32 + acb));
#pragma unroll
            for (int p = 0; p < 2; p++)
                ldsm4(bf[p], bbase + SWZ((brow + p * 16) * 128 + ks * 32 + bcb));
#pragma unroll
            for (int mi = 0; mi < 4; mi++)
#pragma unroll
                for (int ni = 0; ni < 4; ni++)
                    mma16816(acc[mi][ni], af[mi], &bf[ni >> 1][(ni & 1) * 2]);
        }
    }

    // ---------------- epilogue ----------------
    const int mrow0 = blockIdx.y * 128 + wm + (lane >> 2);
    const int ncol0 = blockIdx.x * 128 + wn + (lane & 3) * 2;
    if (!SCATTER) {
        float* Cb = C + (size_t)z * Cz;
#pragma unroll
        for (int mi = 0; mi < 4; mi++) {
#pragma unroll
            for (int ni = 0; ni < 4; ni++) {
                int rr = mrow0 + mi * 16, cc = ncol0 + ni * 8;
                *(float2*)(Cb + (size_t)rr * 2048 + cc) =
                    make_float2(acc[mi][ni][0], acc[mi][ni][1]);
                *(float2*)(Cb + (size_t)(rr + 8) * 2048 + cc) =
                    make_float2(acc[mi][ni][2], acc[mi][ni][3]);
            }
        }
    } else {
#pragma unroll
        for (int mi = 0; mi < 4; mi++) {
#pragma unroll
            for (int half = 0; half < 2; half++) {
                int mloc = blockIdx.y * 128 + wm + mi * 16 + (lane >> 2) + half * 8;
                if (mloc >= routz) continue;
                float wgt = wout[(size_t)z * routz + mloc];
                if (wgt == 0.f) continue;
                int tok = rout[(size_t)z * routz + mloc];
                float* orow = C + (size_t)tok * 2048;
#pragma unroll
                for (int ni = 0; ni < 4; ni++) {
                    int cc = ncol0 + ni * 8;
                    atomicAdd(orow + cc,     wgt * acc[mi][ni][half * 2 + 0]);
                    atomicAdd(orow + cc + 1, wgt * acc[mi][ni][half * 2 + 1]);
                }
            }
        }
    }
}

// ---------------- launch ----------------
extern "C" void kernel_launch(void* const* d_in, const int* in_sizes, int n_in,
                              void* d_out, int out_size) {
    const float* x   = (const float*)d_in[0];
    const float* gw  = (const float*)d_in[1];
    const float* eb  = (const float*)d_in[2];
    const float* sw1 = (const float*)d_in[3];
    const float* sw2 = (const float*)d_in[4];
    const float* rw1 = (const float*)d_in[5];
    const float* rw2 = (const float*)d_in[6];
    float* out = (float*)d_out;

    __half *Xr, *Xg, *Hs, *sw1T, *sw2T, *rw1T, *rw2T;
    float *H2, *selw;
    int* seltok;
    cudaGetSymbolAddress((void**)&Xr, g_Xr);
    cudaGetSymbolAddress((void**)&Xg, g_Xg);
    cudaGetSymbolAddress((void**)&H2, g_H2);
    cudaGetSymbolAddress((void**)&Hs, g_Hs);
    cudaGetSymbolAddress((void**)&sw1T, g_sw1T);
    cudaGetSymbolAddress((void**)&sw2T, g_sw2T);
    cudaGetSymbolAddress((void**)&rw1T, g_rw1T);
    cudaGetSymbolAddress((void**)&rw2T, g_rw2T);
    cudaGetSymbolAddress((void**)&seltok, g_sel_tok);
    cudaGetSymbolAddress((void**)&selw, g_sel_w);

    cudaFuncSetAttribute(gemm_kernel<false>,
                         cudaFuncAttributeMaxDynamicSharedMemorySize, SMEM_BYTES);
    cudaFuncSetAttribute(gemm_kernel<true>,
                         cudaFuncAttributeMaxDynamicSharedMemorySize, SMEM_BYTES);

    // gating + selection (exact fp32)
    gating_kernel<<<TT, 256>>>(x, gw, eb);
    select_kernel<<<EE, 1024>>>();

    // operand prep (fp16 RN)
    roundx_kernel<<<TT * DD / 4 / 256, 256>>>(x);
    transpose_kernel<<<dim3(2 * FF / 32, DD / 32, 1), dim3(32, 8)>>>(sw1, sw1T, DD, 2 * FF);
    transpose_kernel<<<dim3(DD / 32, FF / 32, 1), dim3(32, 8)>>>(sw2, sw2T, FF, DD);
    transpose_kernel<<<dim3(2 * FF / 32, DD / 32, EE), dim3(32, 8)>>>(rw1, rw1T, DD, 2 * FF);
    transpose_kernel<<<dim3(DD / 32, FF / 32, EE), dim3(32, 8)>>>(rw2, rw2T, FF, DD);
    gather_kernel<<<EE * MPAD, 128>>>(x);

    // shared expert
    gemm_kernel<false><<<dim3(16, 64, 1), 256, SMEM_BYTES>>>(
        Xr, sw1T, H2, DD, 0, 0, 0, nullptr, nullptr, 0);
    swiglu_kernel<<<TT * 256 / 256, 256>>>(TT);
    gemm_kernel<false><<<dim3(16, 64, 1), 256, SMEM_BYTES>>>(
        Hs, sw2T, out, FF, 0, 0, 0, nullptr, nullptr, 0);

    // routed experts
    gemm_kernel<false><<<dim3(16, MPAD / 128, EE), 256, SMEM_BYTES>>>(
        Xg, rw1T, H2, DD,
        (size_t)MPAD * DD, (size_t)2 * FF * DD, (size_t)MPAD * 2 * FF,
        nullptr, nullptr, 0);
    swiglu_kernel<<<EE * MPAD, 256>>>(EE * MPAD);
    gemm_kernel<true><<<dim3(16, MPAD / 128, EE), 256, SMEM_BYTES>>>(
        Hs, rw2T, out, FF,
        (size_t)MPAD * FF, (size_t)DD * FF, 0,
        seltok, selw, CAPX);
}

// round 4
// speedup vs baseline: 6.2685x; 1.0303x over previous
#include <cuda_runtime.h>
#include <cuda_fp16.h>
#include <math.h>
#include <stdint.h>

#define TT   8192
#define DD   2048
#define FF   1024
#define EE   7
#define CAPX 1170
#define MPAD 1280
#define NST  3
#define STAGE_BYTES 32768           // A 16KB + B 16KB (fp16, 128x64 each)
#define SMEM_BYTES (NST * STAGE_BYTES)

// ---------------- scratch (device globals) ----------------
__device__ int    g_top[TT * 2];
__device__ float  g_affv[TT * 2];
__device__ int    g_sel_tok[EE * CAPX];
__device__ float  g_sel_w[EE * CAPX];
__device__ __half g_Xr[(size_t)TT * DD];
__device__ __half g_Xg[(size_t)EE * MPAD * DD];
__device__ __half g_Hs[(size_t)EE * MPAD * FF];
__device__ __half g_sw1T[(size_t)2 * FF * DD];
__device__ __half g_sw2T[(size_t)DD * FF];
__device__ __half g_rw1T[(size_t)EE * 2 * FF * DD];
__device__ __half g_rw2T[(size_t)EE * DD * FF];

// ---------------- helpers ----------------
__device__ __forceinline__ uint32_t smem_u32(const void* p) {
    uint32_t a;
    asm("{ .reg .u64 t; cvta.to.shared.u64 t, %1; cvt.u32.u64 %0, t; }" : "=r"(a) : "l"(p));
    return a;
}
__device__ __forceinline__ void cp16(uint32_t d, const void* s) {
    asm volatile("cp.async.cg.shared.global [%0], [%1], 16;" :: "r"(d), "l"(s));
}
#define CP_COMMIT() asm volatile("cp.async.commit_group;" ::: "memory")
#define CP_WAIT1()  asm volatile("cp.async.wait_group 1;" ::: "memory")
#define SWZ(o) ((o) ^ (((o) >> 3) & 0x70))

__device__ __forceinline__ void ldsm4(uint32_t* r, uint32_t addr) {
    asm volatile("ldmatrix.sync.aligned.m8n8.x4.shared.b16 {%0,%1,%2,%3}, [%4];"
                 : "=r"(r[0]), "=r"(r[1]), "=r"(r[2]), "=r"(r[3]) : "r"(addr));
}
__device__ __forceinline__ void mma16816(float* d, const uint32_t* a,
                                         const uint32_t* b) {
    asm volatile(
        "mma.sync.aligned.m16n8k16.row.col.f32.f16.f16.f32 "
        "{%0,%1,%2,%3}, {%4,%5,%6,%7}, {%8,%9}, {%0,%1,%2,%3};"
        : "+f"(d[0]), "+f"(d[1]), "+f"(d[2]), "+f"(d[3])
        : "r"(a[0]), "r"(a[1]), "r"(a[2]), "r"(a[3]), "r"(b[0]), "r"(b[1]));
}

// ---------------- gating (exact fp32) ----------------
__global__ void gating_kernel(const float* __restrict__ x,
                              const float* __restrict__ gw,
                              const float* __restrict__ bias) {
    int t = blockIdx.x;
    const float* xr = x + (size_t)t * DD;
    float s[EE];
#pragma unroll
    for (int e = 0; e < EE; e++) s[e] = 0.f;
    for (int d = threadIdx.x; d < DD; d += 256) {
        float xv = xr[d];
#pragma unroll
        for (int e = 0; e < EE; e++) s[e] = fmaf(xv, gw[d * EE + e], s[e]);
    }
#pragma unroll
    for (int off = 16; off > 0; off >>= 1)
#pragma unroll
        for (int e = 0; e < EE; e++)
            s[e] += __shfl_down_sync(0xffffffffu, s[e], off);
    __shared__ float red[8][EE];
    int warp = threadIdx.x >> 5, lane = threadIdx.x & 31;
    if (lane == 0)
#pragma unroll
        for (int e = 0; e < EE; e++) red[warp][e] = s[e];
    __syncthreads();
    if (threadIdx.x == 0) {
        float aff[EE];
#pragma unroll
        for (int e = 0; e < EE; e++) {
            float v = 0.f;
            for (int w = 0; w < 8; w++) v += red[w][e];
            v += bias[e];
            aff[e] = 1.f / (1.f + expf(-v));
        }
        int e0 = 0;
        for (int e = 1; e < EE; e++) if (aff[e] > aff[e0]) e0 = e;
        int e1 = -1;
        for (int e = 0; e < EE; e++) {
            if (e == e0) continue;
            if (e1 < 0 || aff[e] > aff[e1]) e1 = e;
        }
        g_top[2 * t] = e0;  g_top[2 * t + 1] = e1;
        g_affv[2 * t] = aff[e0];  g_affv[2 * t + 1] = aff[e1];
    }
}

// ---------------- per-expert capacity selection (exact top-CAP) ----------------
__global__ void select_kernel() {
    int e = blockIdx.x;
    __shared__ unsigned int   skey[TT];
    __shared__ unsigned short stok[TT];
    for (int t = threadIdx.x; t < TT; t += blockDim.x) {
        unsigned int key = 0xFFFFFFFFu;
        if (g_top[2 * t] == e)          key = ~__float_as_uint(g_affv[2 * t]);
        else if (g_top[2 * t + 1] == e) key = ~__float_as_uint(g_affv[2 * t + 1]);
        skey[t] = key;
        stok[t] = (unsigned short)t;
    }
    __syncthreads();
    for (int k = 2; k <= TT; k <<= 1) {
        for (int j = k >> 1; j > 0; j >>= 1) {
            for (int i = threadIdx.x; i < TT; i += blockDim.x) {
                int l = i ^ j;
                if (l > i) {
                    bool up = ((i & k) == 0);
                    unsigned int   ki = skey[i], kl = skey[l];
                    unsigned short ti = stok[i], tl = stok[l];
                    bool gt = (ki > kl) || (ki == kl && ti > tl);
                    if (gt == up) {
                        skey[i] = kl; skey[l] = ki;
                        stok[i] = tl; stok[l] = ti;
                    }
                }
            }
            __syncthreads();
        }
    }
    for (int i = threadIdx.x; i < CAPX; i += blockDim.x) {
        unsigned int key = skey[i];
        if (key != 0xFFFFFFFFu) {
            g_sel_tok[e * CAPX + i] = (int)stok[i];
            g_sel_w[e * CAPX + i]   = __uint_as_float(~key);
        } else {
            g_sel_tok[e * CAPX + i] = 0;
            g_sel_w[e * CAPX + i]   = 0.f;
        }
    }
}

// ---------------- prep: x -> fp16 ----------------
__global__ void roundx_kernel(const float* __restrict__ x) {
    size_t i = (size_t)blockIdx.x * blockDim.x + threadIdx.x;
    float4 v = ((const float4*)x)[i];
    __half2 h0 = __floats2half2_rn(v.x, v.y);
    __half2 h1 = __floats2half2_rn(v.z, v.w);
    ((uint2*)g_Xr)[i] = make_uint2(*(uint32_t*)&h0, *(uint32_t*)&h1);
}

// ---------------- prep: transpose [z][K][N] fp32 -> [z][N][K] fp16 ----------------
__global__ void transpose_kernel(const float* __restrict__ in, __half* __restrict__ out,
                                 int K, int N) {
    __shared__ float t[32][33];
    int z = blockIdx.z;
    in  += (size_t)z * K * N;
    out += (size_t)z * N * K;
    int n0 = blockIdx.x * 32, k0 = blockIdx.y * 32;
    int tx = threadIdx.x, ty = threadIdx.y;
#pragma unroll
    for (int i = 0; i < 32; i += 8)
        t[ty + i][tx] = in[(size_t)(k0 + ty + i) * N + n0 + tx];
    __syncthreads();
#pragma unroll
    for (int i = 0; i < 32; i += 8)
        out[(size_t)(n0 + ty + i) * K + k0 + tx] = __float2half_rn(t[tx][ty + i]);
}

// ---------------- gather routed tokens -> fp16 ----------------
__global__ void gather_kernel(const float* __restrict__ x) {
    int r = blockIdx.x;
    int z = r / MPAD, i = r - z * MPAD;
    int tok = (i < CAPX) ? g_sel_tok[z * CAPX + i] : 0;
    const float4* src = (const float4*)(x + (size_t)tok * DD);
    uint2* dst = (uint2*)(g_Xg + (size_t)r * DD);
    for (int c = threadIdx.x; c < DD / 4; c += blockDim.x) {
        float4 v = src[c];
        __half2 h0 = __floats2half2_rn(v.x, v.y);
        __half2 h1 = __floats2half2_rn(v.z, v.w);
        dst[c] = make_uint2(*(uint32_t*)&h0, *(uint32_t*)&h1);
    }
}

// ---------------- fp16 mma.sync GEMM ----------------
// MODE 0: C[M,2048] fp32 store        (GEMM2 dense)
// MODE 1: fused SwiGLU -> Hs fp16     (GEMM1; B rows interleave x1/x2 feature pairs)
// MODE 2: weighted atomicAdd scatter  (GEMM2 routed)
// BM=128 BN=128 BK=64, 256 thr (8 warps, 64x32 warp tiles), 3-stage cp.async.
template <int MODE>
__global__ void __launch_bounds__(256, 2)
gemm_kernel(const __half* __restrict__ A, const __half* __restrict__ B,
            void* __restrict__ Cv, int K, size_t Az, size_t Bz, size_t Cz,
            const int* __restrict__ rout, const float* __restrict__ wout, int routz) {
    extern __shared__ char smem[];
    const uint32_t sb = smem_u32(smem);
    const int tid = threadIdx.x;
    const int lane = tid & 31, wid = tid >> 5;
    const int wm = (wid & 1) * 64;          // warp M offset
    const int wn = (wid >> 1) * 32;         // warp N offset
    const int z = blockIdx.z;

    const __half* Ab = A + (size_t)z * Az + (size_t)blockIdx.y * 128 * K;
    const __half* Bb;
    if (MODE == 1)
        Bb = B + (size_t)z * Bz + (size_t)blockIdx.x * 64 * K;   // feature base
    else
        Bb = B + (size_t)z * Bz + (size_t)blockIdx.x * 128 * K;

    const int kIters = K >> 6;
    const int lrow = tid >> 3;      // 0..31 base row
    const int lc   = tid & 7;       // 16B chunk within 128B row

    auto load_stage = [&](int s, int kt) {
        uint32_t abase = sb + s * STAGE_BYTES;
        uint32_t bbase = abase + 16384;
        const __half* ap = Ab + kt * 64 + lc * 8;
        const __half* bp = Bb + kt * 64 + lc * 8;
#pragma unroll
        for (int j = 0; j < 4; j++) {
            int r = lrow + j * 32;
            cp16(abase + SWZ(r * 128 + lc * 16), ap + (size_t)r * K);
        }
#pragma unroll
        for (int j = 0; j < 4; j++) {
            int r = lrow + j * 32;
            size_t grow;
            if (MODE == 1)  // row r -> feature r>>1, half (r&1): x1 / x2 pair interleave
                grow = (size_t)(r >> 1) + (size_t)(r & 1) * FF;
            else
                grow = (size_t)r;
            cp16(bbase + SWZ(r * 128 + lc * 16), bp + grow * K);
        }
    };

    float acc[4][4][4];
#pragma unroll
    for (int i = 0; i < 4; i++)
#pragma unroll
        for (int j = 0; j < 4; j++)
#pragma unroll
            for (int q = 0; q < 4; q++) acc[i][j][q] = 0.f;

    load_stage(0, 0); CP_COMMIT();
    load_stage(1, 1); CP_COMMIT();

    const int g  = lane >> 3;
    const int l7 = lane & 7;
    const int arow = wm + (g & 1) * 8 + l7;
    const int brow = wn + (g >> 1) * 8 + l7;
    const int acb  = (g >> 1) * 16;
    const int bcb  = (g & 1) * 16;

    for (int kt = 0; kt < kIters; kt++) {
        int s = kt % NST;
        CP_WAIT1();
        __syncthreads();
        if (kt + 2 < kIters) load_stage((kt + 2) % NST, kt + 2);
        CP_COMMIT();

        uint32_t abase = sb + s * STAGE_BYTES;
        uint32_t bbase = abase + 16384;
#pragma unroll
        for (int ks = 0; ks < 4; ks++) {
            uint32_t af[4][4], bf[2][4];
#pragma unroll
            for (int mi = 0; mi < 4; mi++)
                ldsm4(af[mi], abase + SWZ((arow + mi * 16) * 128 + ks * 32 + acb));
#pragma unroll
            for (int p = 0; p < 2; p++)
                ldsm4(bf[p], bbase + SWZ((brow + p * 16) * 128 + ks * 32 + bcb));
#pragma unroll
            for (int mi = 0; mi < 4; mi++)
#pragma unroll
                for (int ni = 0; ni < 4; ni++)
                    mma16816(acc[mi][ni], af[mi], &bf[ni >> 1][(ni & 1) * 2]);
        }
    }

    // ---------------- epilogue ----------------
    if (MODE == 0) {
        float* Cb = (float*)Cv + (size_t)z * Cz;
        const int mrow0 = blockIdx.y * 128 + wm + (lane >> 2);
        const int ncol0 = blockIdx.x * 128 + wn + (lane & 3) * 2;
#pragma unroll
        for (int mi = 0; mi < 4; mi++)
#pragma unroll
            for (int ni = 0; ni < 4; ni++) {
                int rr = mrow0 + mi * 16, cc = ncol0 + ni * 8;
                *(float2*)(Cb + (size_t)rr * 2048 + cc) =
                    make_float2(acc[mi][ni][0], acc[mi][ni][1]);
                *(float2*)(Cb + (size_t)(rr + 8) * 2048 + cc) =
                    make_float2(acc[mi][ni][2], acc[mi][ni][3]);
            }
    } else if (MODE == 1) {
        // acc col pair (2j, 2j+1) = (x1, x2) of feature j
        __half* Hb = (__half*)Cv + (size_t)z * Cz;
        const int f0 = blockIdx.x * 64 + (wn >> 1) + (lane & 3);
        const int m0 = blockIdx.y * 128 + wm + (lane >> 2);
#pragma unroll
        for (int mi = 0; mi < 4; mi++)
#pragma unroll
            for (int half = 0; half < 2; half++) {
                int m = m0 + mi * 16 + half * 8;
                __half* hrow = Hb + (size_t)m * FF;
#pragma unroll
                for (int ni = 0; ni < 4; ni++) {
                    float x1 = acc[mi][ni][half * 2 + 0];
                    float x2 = acc[mi][ni][half * 2 + 1];
                    float o = x1 * (x2 / (1.f + expf(-x2)));
                    hrow[f0 + ni * 4] = __float2half_rn(o);
                }
            }
    } else {
        float* Cb = (float*)Cv;
        const int ncol0 = blockIdx.x * 128 + wn + (lane & 3) * 2;
#pragma unroll
        for (int mi = 0; mi < 4; mi++)
#pragma unroll
            for (int half = 0; half < 2; half++) {
                int mloc = blockIdx.y * 128 + wm + mi * 16 + (lane >> 2) + half * 8;
                if (mloc >= routz) continue;
                float wgt = wout[(size_t)z * routz + mloc];
                if (wgt == 0.f) continue;
                int tok = rout[(size_t)z * routz + mloc];
                float* orow = Cb + (size_t)tok * 2048;
#pragma unroll
                for (int ni = 0; ni < 4; ni++) {
                    int cc = ncol0 + ni * 8;
                    atomicAdd(orow + cc,     wgt * acc[mi][ni][half * 2 + 0]);
                    atomicAdd(orow + cc + 1, wgt * acc[mi][ni][half * 2 + 1]);
                }
            }
    }
}

// ---------------- launch ----------------
extern "C" void kernel_launch(void* const* d_in, const int* in_sizes, int n_in,
                              void* d_out, int out_size) {
    const float* x   = (const float*)d_in[0];
    const float* gw  = (const float*)d_in[1];
    const float* eb  = (const float*)d_in[2];
    const float* sw1 = (const float*)d_in[3];
    const float* sw2 = (const float*)d_in[4];
    const float* rw1 = (const float*)d_in[5];
    const float* rw2 = (const float*)d_in[6];
    float* out = (float*)d_out;

    __half *Xr, *Xg, *Hs, *sw1T, *sw2T, *rw1T, *rw2T;
    float *selw;
    int* seltok;
    cudaGetSymbolAddress((void**)&Xr, g_Xr);
    cudaGetSymbolAddress((void**)&Xg, g_Xg);
    cudaGetSymbolAddress((void**)&Hs, g_Hs);
    cudaGetSymbolAddress((void**)&sw1T, g_sw1T);
    cudaGetSymbolAddress((void**)&sw2T, g_sw2T);
    cudaGetSymbolAddress((void**)&rw1T, g_rw1T);
    cudaGetSymbolAddress((void**)&rw2T, g_rw2T);
    cudaGetSymbolAddress((void**)&seltok, g_sel_tok);
    cudaGetSymbolAddress((void**)&selw, g_sel_w);

    cudaFuncSetAttribute(gemm_kernel<0>,
                         cudaFuncAttributeMaxDynamicSharedMemorySize, SMEM_BYTES);
    cudaFuncSetAttribute(gemm_kernel<1>,
                         cudaFuncAttributeMaxDynamicSharedMemorySize, SMEM_BYTES);
    cudaFuncSetAttribute(gemm_kernel<2>,
                         cudaFuncAttributeMaxDynamicSharedMemorySize, SMEM_BYTES);

    // gating + selection (exact fp32)
    gating_kernel<<<TT, 256>>>(x, gw, eb);
    select_kernel<<<EE, 1024>>>();

    // operand prep (fp16 RN)
    roundx_kernel<<<TT * DD / 4 / 256, 256>>>(x);
    transpose_kernel<<<dim3(2 * FF / 32, DD / 32, 1), dim3(32, 8)>>>(sw1, sw1T, DD, 2 * FF);
    transpose_kernel<<<dim3(DD / 32, FF / 32, 1), dim3(32, 8)>>>(sw2, sw2T, FF, DD);
    transpose_kernel<<<dim3(2 * FF / 32, DD / 32, EE), dim3(32, 8)>>>(rw1, rw1T, DD, 2 * FF);
    transpose_kernel<<<dim3(DD / 32, FF / 32, EE), dim3(32, 8)>>>(rw2, rw2T, FF, DD);
    gather_kernel<<<EE * MPAD, 128>>>(x);

    // shared expert: fused GEMM1+SwiGLU -> Hs ; GEMM2 -> out (dense store)
    gemm_kernel<1><<<dim3(16, 64, 1), 256, SMEM_BYTES>>>(
        Xr, sw1T, Hs, DD, 0, 0, 0, nullptr, nullptr, 0);
    gemm_kernel<0><<<dim3(16, 64, 1), 256, SMEM_BYTES>>>(
        Hs, sw2T, out, FF, 0, 0, 0, nullptr, nullptr, 0);

    // routed experts: fused GEMM1+SwiGLU -> Hs ; GEMM2 -> weighted scatter-add
    gemm_kernel<1><<<dim3(16, MPAD / 128, EE), 256, SMEM_BYTES>>>(
        Xg, rw1T, Hs, DD,
        (size_t)MPAD * DD, (size_t)2 * FF * DD, (size_t)MPAD * FF,
        nullptr, nullptr, 0);
    gemm_kernel<2><<<dim3(16, MPAD / 128, EE), 256, SMEM_BYTES>>>(
        Hs, rw2T, out, FF,
        (size_t)MPAD * FF, (size_t)DD * FF, 0,
        seltok, selw, CAPX);
}

// round 5
// speedup vs baseline: 6.5108x; 1.0387x over previous
#include <cuda_runtime.h>
#include <cuda_fp16.h>
#include <math.h>
#include <stdint.h>

#define TT   8192
#define DD   2048
#define FF   1024
#define EE   7
#define CAPX 1170
#define MPAD 1280
#define NST  3
#define STAGE_BYTES 32768           // A 16KB + B 16KB (fp16, 128x64 each)
#define SMEM_BYTES (NST * STAGE_BYTES)

// ---------------- scratch (device globals) ----------------
__device__ int    g_top[TT * 2];
__device__ float  g_affv[TT * 2];
__device__ int    g_sel_tok[EE * CAPX];
__device__ float  g_sel_w[EE * CAPX];
__device__ __half g_Xr[(size_t)TT * DD];
__device__ __half g_Hs[(size_t)EE * MPAD * FF];
__device__ __half g_sw1T[(size_t)2 * FF * DD];
__device__ __half g_sw2T[(size_t)DD * FF];
__device__ __half g_rw1T[(size_t)EE * 2 * FF * DD];
__device__ __half g_rw2T[(size_t)EE * DD * FF];

// ---------------- helpers ----------------
__device__ __forceinline__ uint32_t smem_u32(const void* p) {
    uint32_t a;
    asm("{ .reg .u64 t; cvta.to.shared.u64 t, %1; cvt.u32.u64 %0, t; }" : "=r"(a) : "l"(p));
    return a;
}
__device__ __forceinline__ void cp16(uint32_t d, const void* s) {
    asm volatile("cp.async.cg.shared.global [%0], [%1], 16;" :: "r"(d), "l"(s));
}
#define CP_COMMIT() asm volatile("cp.async.commit_group;" ::: "memory")
#define CP_WAIT1()  asm volatile("cp.async.wait_group 1;" ::: "memory")
#define SWZ(o) ((o) ^ (((o) >> 3) & 0x70))

__device__ __forceinline__ void ldsm4(uint32_t* r, uint32_t addr) {
    asm volatile("ldmatrix.sync.aligned.m8n8.x4.shared.b16 {%0,%1,%2,%3}, [%4];"
                 : "=r"(r[0]), "=r"(r[1]), "=r"(r[2]), "=r"(r[3]) : "r"(addr));
}
__device__ __forceinline__ void mma16816(float* d, const uint32_t* a,
                                         const uint32_t* b) {
    asm volatile(
        "mma.sync.aligned.m16n8k16.row.col.f32.f16.f16.f32 "
        "{%0,%1,%2,%3}, {%4,%5,%6,%7}, {%8,%9}, {%0,%1,%2,%3};"
        : "+f"(d[0]), "+f"(d[1]), "+f"(d[2]), "+f"(d[3])
        : "r"(a[0]), "r"(a[1]), "r"(a[2]), "r"(a[3]), "r"(b[0]), "r"(b[1]));
}

// ---------------- gating (exact fp32) ----------------
__global__ void gating_kernel(const float* __restrict__ x,
                              const float* __restrict__ gw,
                              const float* __restrict__ bias) {
    int t = blockIdx.x;
    const float* xr = x + (size_t)t * DD;
    float s[EE];
#pragma unroll
    for (int e = 0; e < EE; e++) s[e] = 0.f;
    for (int d = threadIdx.x; d < DD; d += 256) {
        float xv = xr[d];
#pragma unroll
        for (int e = 0; e < EE; e++) s[e] = fmaf(xv, gw[d * EE + e], s[e]);
    }
#pragma unroll
    for (int off = 16; off > 0; off >>= 1)
#pragma unroll
        for (int e = 0; e < EE; e++)
            s[e] += __shfl_down_sync(0xffffffffu, s[e], off);
    __shared__ float red[8][EE];
    int warp = threadIdx.x >> 5, lane = threadIdx.x & 31;
    if (lane == 0)
#pragma unroll
        for (int e = 0; e < EE; e++) red[warp][e] = s[e];
    __syncthreads();
    if (threadIdx.x == 0) {
        float aff[EE];
#pragma unroll
        for (int e = 0; e < EE; e++) {
            float v = 0.f;
            for (int w = 0; w < 8; w++) v += red[w][e];
            v += bias[e];
            aff[e] = 1.f / (1.f + expf(-v));
        }
        int e0 = 0;
        for (int e = 1; e < EE; e++) if (aff[e] > aff[e0]) e0 = e;
        int e1 = -1;
        for (int e = 0; e < EE; e++) {
            if (e == e0) continue;
            if (e1 < 0 || aff[e] > aff[e1]) e1 = e;
        }
        g_top[2 * t] = e0;  g_top[2 * t + 1] = e1;
        g_affv[2 * t] = aff[e0];  g_affv[2 * t + 1] = aff[e1];
    }
}

// ---------------- per-expert capacity selection (exact top-CAP) ----------------
__global__ void select_kernel() {
    int e = blockIdx.x;
    __shared__ unsigned int   skey[TT];
    __shared__ unsigned short stok[TT];
    for (int t = threadIdx.x; t < TT; t += blockDim.x) {
        unsigned int key = 0xFFFFFFFFu;
        if (g_top[2 * t] == e)          key = ~__float_as_uint(g_affv[2 * t]);
        else if (g_top[2 * t + 1] == e) key = ~__float_as_uint(g_affv[2 * t + 1]);
        skey[t] = key;
        stok[t] = (unsigned short)t;
    }
    __syncthreads();
    for (int k = 2; k <= TT; k <<= 1) {
        for (int j = k >> 1; j > 0; j >>= 1) {
            for (int i = threadIdx.x; i < TT; i += blockDim.x) {
                int l = i ^ j;
                if (l > i) {
                    bool up = ((i & k) == 0);
                    unsigned int   ki = skey[i], kl = skey[l];
                    unsigned short ti = stok[i], tl = stok[l];
                    bool gt = (ki > kl) || (ki == kl && ti > tl);
                    if (gt == up) {
                        skey[i] = kl; skey[l] = ki;
                        stok[i] = tl; stok[l] = ti;
                    }
                }
            }
            __syncthreads();
        }
    }
    for (int i = threadIdx.x; i < CAPX; i += blockDim.x) {
        unsigned int key = skey[i];
        if (key != 0xFFFFFFFFu) {
            g_sel_tok[e * CAPX + i] = (int)stok[i];
            g_sel_w[e * CAPX + i]   = __uint_as_float(~key);
        } else {
            g_sel_tok[e * CAPX + i] = 0;
            g_sel_w[e * CAPX + i]   = 0.f;
        }
    }
}

// ---------------- prep: x -> fp16 ----------------
__global__ void roundx_kernel(const float* __restrict__ x) {
    size_t i = (size_t)blockIdx.x * blockDim.x + threadIdx.x;
    float4 v = ((const float4*)x)[i];
    __half2 h0 = __floats2half2_rn(v.x, v.y);
    __half2 h1 = __floats2half2_rn(v.z, v.w);
    ((uint2*)g_Xr)[i] = make_uint2(*(uint32_t*)&h0, *(uint32_t*)&h1);
}

// ---------------- fast transpose-convert: [K,N] fp32 -> [N,K] fp16 ----------------
// 64x64 tiles, coalesced fp32 loads, coalesced half2 (128B/warp) stores.
// z==0 -> (in0,out0); z>=1 -> (inZ + (z-1)*K*N, outZ + (z-1)*K*N)
__global__ void __launch_bounds__(256)
convT_kernel(const float* __restrict__ in0, const float* __restrict__ inZ,
             __half* __restrict__ out0, __half* __restrict__ outZ,
             int K, int N) {
    __shared__ float t[64][65];
    int z = blockIdx.z;
    const float* in = (z == 0) ? in0 : inZ + (size_t)(z - 1) * K * N;
    __half* out = (z == 0) ? out0 : outZ + (size_t)(z - 1) * K * N;
    int n0 = blockIdx.x * 64, k0 = blockIdx.y * 64;
    int r = threadIdx.x >> 4;              // 0..15
    int c4 = (threadIdx.x & 15) * 4;       // 0,4,...,60
#pragma unroll
    for (int p = 0; p < 4; p++) {
        int row = r + p * 16;
        float4 v = *(const float4*)(in + (size_t)(k0 + row) * N + n0 + c4);
        t[row][c4 + 0] = v.x; t[row][c4 + 1] = v.y;
        t[row][c4 + 2] = v.z; t[row][c4 + 3] = v.w;
    }
    __syncthreads();
    int warp = threadIdx.x >> 5, lane = threadIdx.x & 31;
#pragma unroll
    for (int p = 0; p < 8; p++) {
        int n = warp * 8 + p;
        __half2 h = __floats2half2_rn(t[2 * lane][n], t[2 * lane + 1][n]);
        *(__half2*)(out + (size_t)(n0 + n) * K + k0 + 2 * lane) = h;
    }
}

// ---------------- fp16 mma.sync GEMM ----------------
// MODE 0: C[M,2048] fp32 store        (GEMM2 dense)
// MODE 1: fused SwiGLU -> Hs fp16     (GEMM1; B rows interleave x1/x2 feature pairs)
// MODE 2: weighted atomicAdd scatter  (GEMM2 routed)
// GATHER: A rows gathered via gidx (token ids); rows >= gN use row 0.
// BM=128 BN=128 BK=64, 256 thr (8 warps, 64x32 warp tiles), 3-stage cp.async.
template <int MODE, bool GATHER>
__global__ void __launch_bounds__(256, 2)
gemm_kernel(const __half* __restrict__ A, const __half* __restrict__ B,
            void* __restrict__ Cv, int K, size_t Az, size_t Bz, size_t Cz,
            const int* __restrict__ rout, const float* __restrict__ wout, int routz,
            const int* __restrict__ gidx, int gN) {
    extern __shared__ char smem[];
    const uint32_t sb = smem_u32(smem);
    const int tid = threadIdx.x;
    const int lane = tid & 31, wid = tid >> 5;
    const int wm = (wid & 1) * 64;          // warp M offset
    const int wn = (wid >> 1) * 32;         // warp N offset
    const int z = blockIdx.z;

    const __half* Bb;
    if (MODE == 1)
        Bb = B + (size_t)z * Bz + (size_t)blockIdx.x * 64 * K;   // feature base
    else
        Bb = B + (size_t)z * Bz + (size_t)blockIdx.x * 128 * K;

    const int kIters = K >> 6;
    const int lrow = tid >> 3;      // 0..31 base row
    const int lc   = tid & 7;       // 16B chunk within 128B row

    // per-thread A/B row base pointers (resolved once)
    const __half* ap[4];
    const __half* bp[4];
#pragma unroll
    for (int j = 0; j < 4; j++) {
        int r = lrow + j * 32;
        int am = blockIdx.y * 128 + r;
        size_t arow;
        if (GATHER)
            arow = (size_t)((am < gN) ? gidx[(size_t)z * gN + am] : 0);
        else
            arow = (size_t)am;
        ap[j] = A + (GATHER ? 0 : (size_t)z * Az) + arow * K + lc * 8;
        size_t grow;
        if (MODE == 1)
            grow = (size_t)(r >> 1) + (size_t)(r & 1) * FF;
        else
            grow = (size_t)r;
        bp[j] = Bb + grow * K + lc * 8;
    }

    auto load_stage = [&](int s, int kt) {
        uint32_t abase = sb + s * STAGE_BYTES;
        uint32_t bbase = abase + 16384;
        const int ko = kt * 64;
#pragma unroll
        for (int j = 0; j < 4; j++) {
            int r = lrow + j * 32;
            cp16(abase + SWZ(r * 128 + lc * 16), ap[j] + ko);
        }
#pragma unroll
        for (int j = 0; j < 4; j++) {
            int r = lrow + j * 32;
            cp16(bbase + SWZ(r * 128 + lc * 16), bp[j] + ko);
        }
    };

    float acc[4][4][4];
#pragma unroll
    for (int i = 0; i < 4; i++)
#pragma unroll
        for (int j = 0; j < 4; j++)
#pragma unroll
            for (int q = 0; q < 4; q++) acc[i][j][q] = 0.f;

    load_stage(0, 0); CP_COMMIT();
    load_stage(1, 1); CP_COMMIT();

    const int g  = lane >> 3;
    const int l7 = lane & 7;
    const int arow = wm + (g & 1) * 8 + l7;
    const int brow = wn + (g >> 1) * 8 + l7;
    const int acb  = (g >> 1) * 16;
    const int bcb  = (g & 1) * 16;

    for (int kt = 0; kt < kIters; kt++) {
        int s = kt % NST;
        CP_WAIT1();
        __syncthreads();
        if (kt + 2 < kIters) load_stage((kt + 2) % NST, kt + 2);
        CP_COMMIT();

        uint32_t abase = sb + s * STAGE_BYTES;
        uint32_t bbase = abase + 16384;
#pragma unroll
        for (int ks = 0; ks < 4; ks++) {
            uint32_t af[4][4], bf[2][4];
#pragma unroll
            for (int mi = 0; mi < 4; mi++)
                ldsm4(af[mi], abase + SWZ((arow + mi * 16) * 128 + ks * 32 + acb));
#pragma unroll
            for (int p = 0; p < 2; p++)
                ldsm4(bf[p], bbase + SWZ((brow + p * 16) * 128 + ks * 32 + bcb));
#pragma unroll
            for (int mi = 0; mi < 4; mi++)
#pragma unroll
                for (int ni = 0; ni < 4; ni++)
                    mma16816(acc[mi][ni], af[mi], &bf[ni >> 1][(ni & 1) * 2]);
        }
    }

    // ---------------- epilogue ----------------
    if (MODE == 0) {
        float* Cb = (float*)Cv + (size_t)z * Cz;
        const int mrow0 = blockIdx.y * 128 + wm + (lane >> 2);
        const int ncol0 = blockIdx.x * 128 + wn + (lane & 3) * 2;
#pragma unroll
        for (int mi = 0; mi < 4; mi++)
#pragma unroll
            for (int ni = 0; ni < 4; ni++) {
                int rr = mrow0 + mi * 16, cc = ncol0 + ni * 8;
                *(float2*)(Cb + (size_t)rr * 2048 + cc) =
                    make_float2(acc[mi][ni][0], acc[mi][ni][1]);
                *(float2*)(Cb + (size_t)(rr + 8) * 2048 + cc) =
                    make_float2(acc[mi][ni][2], acc[mi][ni][3]);
            }
    } else if (MODE == 1) {
        // acc col pair (2j, 2j+1) = (x1, x2) of feature j
        __half* Hb = (__half*)Cv + (size_t)z * Cz;
        const int f0 = blockIdx.x * 64 + (wn >> 1) + (lane & 3);
        const int m0 = blockIdx.y * 128 + wm + (lane >> 2);
#pragma unroll
        for (int mi = 0; mi < 4; mi++)
#pragma unroll
            for (int half = 0; half < 2; half++) {
                int m = m0 + mi * 16 + half * 8;
                __half* hrow = Hb + (size_t)m * FF;
#pragma unroll
                for (int ni = 0; ni < 4; ni++) {
                    float x1 = acc[mi][ni][half * 2 + 0];
                    float x2 = acc[mi][ni][half * 2 + 1];
                    float o = x1 * (x2 / (1.f + expf(-x2)));
                    hrow[f0 + ni * 4] = __float2half_rn(o);
                }
            }
    } else {
        float* Cb = (float*)Cv;
        const int ncol0 = blockIdx.x * 128 + wn + (lane & 3) * 2;
#pragma unroll
        for (int mi = 0; mi < 4; mi++)
#pragma unroll
            for (int half = 0; half < 2; half++) {
                int mloc = blockIdx.y * 128 + wm + mi * 16 + (lane >> 2) + half * 8;
                if (mloc >= routz) continue;
                float wgt = wout[(size_t)z * routz + mloc];
                if (wgt == 0.f) continue;
                int tok = rout[(size_t)z * routz + mloc];
                float* orow = Cb + (size_t)tok * 2048;
#pragma unroll
                for (int ni = 0; ni < 4; ni++) {
                    int cc = ncol0 + ni * 8;
                    atomicAdd(orow + cc,     wgt * acc[mi][ni][half * 2 + 0]);
                    atomicAdd(orow + cc + 1, wgt * acc[mi][ni][half * 2 + 1]);
                }
            }
    }
}

// ---------------- launch ----------------
extern "C" void kernel_launch(void* const* d_in, const int* in_sizes, int n_in,
                              void* d_out, int out_size) {
    const float* x   = (const float*)d_in[0];
    const float* gw  = (const float*)d_in[1];
    const float* eb  = (const float*)d_in[2];
    const float* sw1 = (const float*)d_in[3];
    const float* sw2 = (const float*)d_in[4];
    const float* rw1 = (const float*)d_in[5];
    const float* rw2 = (const float*)d_in[6];
    float* out = (float*)d_out;

    __half *Xr, *Hs, *sw1T, *sw2T, *rw1T, *rw2T;
    float *selw;
    int* seltok;
    cudaGetSymbolAddress((void**)&Xr, g_Xr);
    cudaGetSymbolAddress((void**)&Hs, g_Hs);
    cudaGetSymbolAddress((void**)&sw1T, g_sw1T);
    cudaGetSymbolAddress((void**)&sw2T, g_sw2T);
    cudaGetSymbolAddress((void**)&rw1T, g_rw1T);
    cudaGetSymbolAddress((void**)&rw2T, g_rw2T);
    cudaGetSymbolAddress((void**)&seltok, g_sel_tok);
    cudaGetSymbolAddress((void**)&selw, g_sel_w);

    cudaFuncSetAttribute((const void*)gemm_kernel<0, false>,
                         cudaFuncAttributeMaxDynamicSharedMemorySize, SMEM_BYTES);
    cudaFuncSetAttribute((const void*)gemm_kernel<1, false>,
                         cudaFuncAttributeMaxDynamicSharedMemorySize, SMEM_BYTES);
    cudaFuncSetAttribute((const void*)gemm_kernel<1, true>,
                         cudaFuncAttributeMaxDynamicSharedMemorySize, SMEM_BYTES);
    cudaFuncSetAttribute((const void*)gemm_kernel<2, false>,
                         cudaFuncAttributeMaxDynamicSharedMemorySize, SMEM_BYTES);

    // 1: gating  2: selection (exact fp32)
    gating_kernel<<<TT, 256>>>(x, gw, eb);
    select_kernel<<<EE, 1024>>>();

    // 3: x -> fp16
    roundx_kernel<<<TT * DD / 4 / 256, 256>>>(x);

    // 4,5: weight transpose-convert (w1 group: sw1+rw1 ; w2 group: sw2+rw2)
    convT_kernel<<<dim3(2 * FF / 64, DD / 64, 1 + EE), 256>>>(
        sw1, rw1, sw1T, rw1T, DD, 2 * FF);
    convT_kernel<<<dim3(DD / 64, FF / 64, 1 + EE), 256>>>(
        sw2, rw2, sw2T, rw2T, FF, DD);

    // 6: shared GEMM1 (fused SwiGLU)  [ncu capture slot]
    gemm_kernel<1, false><<<dim3(16, 64, 1), 256, SMEM_BYTES>>>(
        Xr, sw1T, Hs, DD, 0, 0, 0, nullptr, nullptr, 0, nullptr, 0);
    // 7: shared GEMM2 (dense store)
    gemm_kernel<0, false><<<dim3(16, 64, 1), 256, SMEM_BYTES>>>(
        Hs, sw2T, out, FF, 0, 0, 0, nullptr, nullptr, 0, nullptr, 0);

    // 8: routed GEMM1 (gathered A, fused SwiGLU)
    gemm_kernel<1, true><<<dim3(16, MPAD / 128, EE), 256, SMEM_BYTES>>>(
        Xr, rw1T, Hs, DD,
        0, (size_t)2 * FF * DD, (size_t)MPAD * FF,
        nullptr, nullptr, 0, seltok, CAPX);
    // 9: routed GEMM2 (weighted scatter-add)
    gemm_kernel<2, false><<<dim3(16, MPAD / 128, EE), 256, SMEM_BYTES>>>(
        Hs, rw2T, out, FF,
        (size_t)MPAD * FF, (size_t)DD * FF, 0,
        seltok, selw, CAPX, nullptr, 0);
}

// round 6
// speedup vs baseline: 7.0202x; 1.0782x over previous
#include <cuda_runtime.h>
#include <cuda_fp16.h>
#include <math.h>
#include <stdint.h>

#define TT   8192
#define DD   2048
#define FF   1024
#define EE   7
#define CAPX 1170
#define MPAD 1280
#define NST  3
#define STAGE_BYTES 32768           // A 16KB + B 16KB (fp16, 128x64 each)
#define SMEM_BYTES (NST * STAGE_BYTES)

// ---------------- scratch (device globals) ----------------
__device__ int    g_top[TT * 2];
__device__ float  g_affv[TT * 2];
__device__ int    g_sel_tok[EE * CAPX];
__device__ float  g_sel_w[EE * CAPX];
__device__ __half g_Xr[(size_t)TT * DD];
__device__ __half g_Hs[(size_t)EE * MPAD * FF];
__device__ __half g_sw1T[(size_t)2 * FF * DD];
__device__ __half g_sw2T[(size_t)DD * FF];
__device__ __half g_rw1T[(size_t)EE * 2 * FF * DD];
__device__ __half g_rw2T[(size_t)EE * DD * FF];

// ---------------- helpers ----------------
__device__ __forceinline__ uint32_t smem_u32(const void* p) {
    uint32_t a;
    asm("{ .reg .u64 t; cvta.to.shared.u64 t, %1; cvt.u32.u64 %0, t; }" : "=r"(a) : "l"(p));
    return a;
}
__device__ __forceinline__ void cp16(uint32_t d, const void* s) {
    asm volatile("cp.async.cg.shared.global [%0], [%1], 16;" :: "r"(d), "l"(s));
}
#define CP_COMMIT() asm volatile("cp.async.commit_group;" ::: "memory")
#define CP_WAIT1()  asm volatile("cp.async.wait_group 1;" ::: "memory")
#define SWZ(o) ((o) ^ (((o) >> 3) & 0x70))

__device__ __forceinline__ void ldsm4(uint32_t* r, uint32_t addr) {
    asm volatile("ldmatrix.sync.aligned.m8n8.x4.shared.b16 {%0,%1,%2,%3}, [%4];"
                 : "=r"(r[0]), "=r"(r[1]), "=r"(r[2]), "=r"(r[3]) : "r"(addr));
}
__device__ __forceinline__ void mma16816(float* d, const uint32_t* a,
                                         const uint32_t* b) {
    asm volatile(
        "mma.sync.aligned.m16n8k16.row.col.f32.f16.f16.f32 "
        "{%0,%1,%2,%3}, {%4,%5,%6,%7}, {%8,%9}, {%0,%1,%2,%3};"
        : "+f"(d[0]), "+f"(d[1]), "+f"(d[2]), "+f"(d[3])
        : "r"(a[0]), "r"(a[1]), "r"(a[2]), "r"(a[3]), "r"(b[0]), "r"(b[1]));
}

// ---------------- gating (exact fp32) ----------------
__global__ void gating_kernel(const float* __restrict__ x,
                              const float* __restrict__ gw,
                              const float* __restrict__ bias) {
    int t = blockIdx.x;
    const float* xr = x + (size_t)t * DD;
    float s[EE];
#pragma unroll
    for (int e = 0; e < EE; e++) s[e] = 0.f;
    for (int d = threadIdx.x; d < DD; d += 256) {
        float xv = xr[d];
#pragma unroll
        for (int e = 0; e < EE; e++) s[e] = fmaf(xv, gw[d * EE + e], s[e]);
    }
#pragma unroll
    for (int off = 16; off > 0; off >>= 1)
#pragma unroll
        for (int e = 0; e < EE; e++)
            s[e] += __shfl_down_sync(0xffffffffu, s[e], off);
    __shared__ float red[8][EE];
    int warp = threadIdx.x >> 5, lane = threadIdx.x & 31;
    if (lane == 0)
#pragma unroll
        for (int e = 0; e < EE; e++) red[warp][e] = s[e];
    __syncthreads();
    if (threadIdx.x == 0) {
        float aff[EE];
#pragma unroll
        for (int e = 0; e < EE; e++) {
            float v = 0.f;
            for (int w = 0; w < 8; w++) v += red[w][e];
            v += bias[e];
            aff[e] = 1.f / (1.f + expf(-v));
        }
        int e0 = 0;
        for (int e = 1; e < EE; e++) if (aff[e] > aff[e0]) e0 = e;
        int e1 = -1;
        for (int e = 0; e < EE; e++) {
            if (e == e0) continue;
            if (e1 < 0 || aff[e] > aff[e1]) e1 = e;
        }
        g_top[2 * t] = e0;  g_top[2 * t + 1] = e1;
        g_affv[2 * t] = aff[e0];  g_affv[2 * t + 1] = aff[e1];
    }
}

// ---------------- per-expert capacity selection (exact top-CAP) ----------------
__global__ void select_kernel() {
    int e = blockIdx.x;
    __shared__ unsigned int   skey[TT];
    __shared__ unsigned short stok[TT];
    for (int t = threadIdx.x; t < TT; t += blockDim.x) {
        unsigned int key = 0xFFFFFFFFu;
        if (g_top[2 * t] == e)          key = ~__float_as_uint(g_affv[2 * t]);
        else if (g_top[2 * t + 1] == e) key = ~__float_as_uint(g_affv[2 * t + 1]);
        skey[t] = key;
        stok[t] = (unsigned short)t;
    }
    __syncthreads();
    for (int k = 2; k <= TT; k <<= 1) {
        for (int j = k >> 1; j > 0; j >>= 1) {
            for (int i = threadIdx.x; i < TT; i += blockDim.x) {
                int l = i ^ j;
                if (l > i) {
                    bool up = ((i & k) == 0);
                    unsigned int   ki = skey[i], kl = skey[l];
                    unsigned short ti = stok[i], tl = stok[l];
                    bool gt = (ki > kl) || (ki == kl && ti > tl);
                    if (gt == up) {
                        skey[i] = kl; skey[l] = ki;
                        stok[i] = tl; stok[l] = ti;
                    }
                }
            }
            __syncthreads();
        }
    }
    for (int i = threadIdx.x; i < CAPX; i += blockDim.x) {
        unsigned int key = skey[i];
        if (key != 0xFFFFFFFFu) {
            g_sel_tok[e * CAPX + i] = (int)stok[i];
            g_sel_w[e * CAPX + i]   = __uint_as_float(~key);
        } else {
            g_sel_tok[e * CAPX + i] = 0;
            g_sel_w[e * CAPX + i]   = 0.f;
        }
    }
}

// ---------------- prep: x -> fp16 ----------------
__global__ void roundx_kernel(const float* __restrict__ x) {
    size_t i = (size_t)blockIdx.x * blockDim.x + threadIdx.x;
    float4 v = ((const float4*)x)[i];
    __half2 h0 = __floats2half2_rn(v.x, v.y);
    __half2 h1 = __floats2half2_rn(v.z, v.w);
    ((uint2*)g_Xr)[i] = make_uint2(*(uint32_t*)&h0, *(uint32_t*)&h1);
}

// ---------------- fast transpose-convert: [K,N] fp32 -> [N,K] fp16 ----------------
__global__ void __launch_bounds__(256)
convT_kernel(const float* __restrict__ in0, const float* __restrict__ inZ,
             __half* __restrict__ out0, __half* __restrict__ outZ,
             int K, int N) {
    __shared__ float t[64][65];
    int z = blockIdx.z;
    const float* in = (z == 0) ? in0 : inZ + (size_t)(z - 1) * K * N;
    __half* out = (z == 0) ? out0 : outZ + (size_t)(z - 1) * K * N;
    int n0 = blockIdx.x * 64, k0 = blockIdx.y * 64;
    int r = threadIdx.x >> 4;
    int c4 = (threadIdx.x & 15) * 4;
#pragma unroll
    for (int p = 0; p < 4; p++) {
        int row = r + p * 16;
        float4 v = *(const float4*)(in + (size_t)(k0 + row) * N + n0 + c4);
        t[row][c4 + 0] = v.x; t[row][c4 + 1] = v.y;
        t[row][c4 + 2] = v.z; t[row][c4 + 3] = v.w;
    }
    __syncthreads();
    int warp = threadIdx.x >> 5, lane = threadIdx.x & 31;
#pragma unroll
    for (int p = 0; p < 8; p++) {
        int n = warp * 8 + p;
        __half2 h = __floats2half2_rn(t[2 * lane][n], t[2 * lane + 1][n]);
        *(__half2*)(out + (size_t)(n0 + n) * K + k0 + 2 * lane) = h;
    }
}

// ---------------- fp16 mma.sync GEMM ----------------
// MODE 0: C[M,2048] fp32 store        (GEMM2 dense)
// MODE 1: fused SwiGLU -> Hs fp16     (GEMM1; B rows interleave x1/x2 feature pairs)
// MODE 2: weighted atomicAdd scatter  (GEMM2 routed)
// GATHER: A rows gathered via gidx (token ids); rows >= gN use row 0.
// BM=128 BN=128 BK=64, 128 thr (4 warps of 64x64), 3-stage cp.async, 2 CTA/SM.
template <int MODE, bool GATHER>
__global__ void __launch_bounds__(128, 2)
gemm_kernel(const __half* __restrict__ A, const __half* __restrict__ B,
            void* __restrict__ Cv, int K, size_t Az, size_t Bz, size_t Cz,
            const int* __restrict__ rout, const float* __restrict__ wout, int routz,
            const int* __restrict__ gidx, int gN) {
    extern __shared__ char smem[];
    const uint32_t sb = smem_u32(smem);
    const int tid = threadIdx.x;
    const int lane = tid & 31, wid = tid >> 5;
    const int wm = (wid & 1) * 64;          // warp M offset
    const int wn = (wid >> 1) * 64;         // warp N offset
    const int z = blockIdx.z;

    const __half* Ab0 = A + (GATHER ? 0 : (size_t)z * Az);
    const __half* Bb;
    if (MODE == 1)
        Bb = B + (size_t)z * Bz + (size_t)blockIdx.x * 64 * K;   // feature base
    else
        Bb = B + (size_t)z * Bz + (size_t)blockIdx.x * 128 * K;

    const int kIters = K >> 6;
    const int lrow = tid >> 3;      // 0..15 base row
    const int lc   = tid & 7;       // 16B chunk within 128B row

    // A global row index per j (gather resolved once); B row mapping is static
    int arow_[8];
#pragma unroll
    for (int j = 0; j < 8; j++) {
        int am = blockIdx.y * 128 + lrow + j * 16;
        if (GATHER)
            arow_[j] = (am < gN) ? gidx[(size_t)z * gN + am] : 0;
        else
            arow_[j] = am;
    }

    auto load_stage = [&](int s, int kt) {
        uint32_t abase = sb + s * STAGE_BYTES;
        uint32_t bbase = abase + 16384;
        const int ko = kt * 64 + lc * 8;
#pragma unroll
        for (int j = 0; j < 8; j++) {
            int r = lrow + j * 16;
            cp16(abase + SWZ(r * 128 + lc * 16), Ab0 + (size_t)arow_[j] * K + ko);
        }
#pragma unroll
        for (int j = 0; j < 8; j++) {
            int r = lrow + j * 16;
            size_t grow;
            if (MODE == 1)
                grow = (size_t)(r >> 1) + (size_t)(r & 1) * FF;
            else
                grow = (size_t)r;
            cp16(bbase + SWZ(r * 128 + lc * 16), Bb + grow * K + ko);
        }
    };

    float acc[4][8][4];
#pragma unroll
    for (int i = 0; i < 4; i++)
#pragma unroll
        for (int j = 0; j < 8; j++)
#pragma unroll
            for (int q = 0; q < 4; q++) acc[i][j][q] = 0.f;

    load_stage(0, 0); CP_COMMIT();
    load_stage(1, 1); CP_COMMIT();

    const int g  = lane >> 3;
    const int l7 = lane & 7;
    const int arow = wm + (g & 1) * 8 + l7;
    const int brow = wn + (g >> 1) * 8 + l7;
    const int acb  = (g >> 1) * 16;
    const int bcb  = (g & 1) * 16;

    for (int kt = 0; kt < kIters; kt++) {
        int s = kt % NST;
        CP_WAIT1();
        __syncthreads();
        if (kt + 2 < kIters) load_stage((kt + 2) % NST, kt + 2);
        CP_COMMIT();

        uint32_t abase = sb + s * STAGE_BYTES;
        uint32_t bbase = abase + 16384;
#pragma unroll
        for (int ks = 0; ks < 4; ks++) {
            uint32_t af[4][4], bf[4][4];
#pragma unroll
            for (int mi = 0; mi < 4; mi++)
                ldsm4(af[mi], abase + SWZ((arow + mi * 16) * 128 + ks * 32 + acb));
#pragma unroll
            for (int p = 0; p < 4; p++)
                ldsm4(bf[p], bbase + SWZ((brow + p * 16) * 128 + ks * 32 + bcb));
#pragma unroll
            for (int mi = 0; mi < 4; mi++)
#pragma unroll
                for (int ni = 0; ni < 8; ni++)
                    mma16816(acc[mi][ni], af[mi], &bf[ni >> 1][(ni & 1) * 2]);
        }
    }

    // ---------------- epilogue ----------------
    if (MODE == 0) {
        float* Cb = (float*)Cv + (size_t)z * Cz;
        const int mrow0 = blockIdx.y * 128 + wm + (lane >> 2);
        const int ncol0 = blockIdx.x * 128 + wn + (lane & 3) * 2;
#pragma unroll
        for (int mi = 0; mi < 4; mi++)
#pragma unroll
            for (int ni = 0; ni < 8; ni++) {
                int rr = mrow0 + mi * 16, cc = ncol0 + ni * 8;
                *(float2*)(Cb + (size_t)rr * 2048 + cc) =
                    make_float2(acc[mi][ni][0], acc[mi][ni][1]);
                *(float2*)(Cb + (size_t)(rr + 8) * 2048 + cc) =
                    make_float2(acc[mi][ni][2], acc[mi][ni][3]);
            }
    } else if (MODE == 1) {
        // acc col pair (2j, 2j+1) = (x1, x2) of feature j
        __half* Hb = (__half*)Cv + (size_t)z * Cz;
        const int f0 = blockIdx.x * 64 + (wn >> 1) + (lane & 3);
        const int m0 = blockIdx.y * 128 + wm + (lane >> 2);
#pragma unroll
        for (int mi = 0; mi < 4; mi++)
#pragma unroll
            for (int half = 0; half < 2; half++) {
                int m = m0 + mi * 16 + half * 8;
                __half* hrow = Hb + (size_t)m * FF;
#pragma unroll
                for (int ni = 0; ni < 8; ni++) {
                    float x1 = acc[mi][ni][half * 2 + 0];
                    float x2 = acc[mi][ni][half * 2 + 1];
                    float o = x1 * (x2 / (1.f + expf(-x2)));
                    hrow[f0 + ni * 4] = __float2half_rn(o);
                }
            }
    } else {
        float* Cb = (float*)Cv;
        const int ncol0 = blockIdx.x * 128 + wn + (lane & 3) * 2;
#pragma unroll
        for (int mi = 0; mi < 4; mi++)
#pragma unroll
            for (int half = 0; half < 2; half++) {
                int mloc = blockIdx.y * 128 + wm + mi * 16 + (lane >> 2) + half * 8;
                if (mloc >= routz) continue;
                float wgt = wout[(size_t)z * routz + mloc];
                if (wgt == 0.f) continue;
                int tok = rout[(size_t)z * routz + mloc];
                float* orow = Cb + (size_t)tok * 2048;
#pragma unroll
                for (int ni = 0; ni < 8; ni++) {
                    int cc = ncol0 + ni * 8;
                    atomicAdd(orow + cc,     wgt * acc[mi][ni][half * 2 + 0]);
                    atomicAdd(orow + cc + 1, wgt * acc[mi][ni][half * 2 + 1]);
                }
            }
    }
}

// ---------------- launch ----------------
extern "C" void kernel_launch(void* const* d_in, const int* in_sizes, int n_in,
                              void* d_out, int out_size) {
    const float* x   = (const float*)d_in[0];
    const float* gw  = (const float*)d_in[1];
    const float* eb  = (const float*)d_in[2];
    const float* sw1 = (const float*)d_in[3];
    const float* sw2 = (const float*)d_in[4];
    const float* rw1 = (const float*)d_in[5];
    const float* rw2 = (const float*)d_in[6];
    float* out = (float*)d_out;

    __half *Xr, *Hs, *sw1T, *sw2T, *rw1T, *rw2T;
    float *selw;
    int* seltok;
    cudaGetSymbolAddress((void**)&Xr, g_Xr);
    cudaGetSymbolAddress((void**)&Hs, g_Hs);
    cudaGetSymbolAddress((void**)&sw1T, g_sw1T);
    cudaGetSymbolAddress((void**)&sw2T, g_sw2T);
    cudaGetSymbolAddress((void**)&rw1T, g_rw1T);
    cudaGetSymbolAddress((void**)&rw2T, g_rw2T);
    cudaGetSymbolAddress((void**)&seltok, g_sel_tok);
    cudaGetSymbolAddress((void**)&selw, g_sel_w);

    cudaFuncSetAttribute((const void*)gemm_kernel<0, false>,
                         cudaFuncAttributeMaxDynamicSharedMemorySize, SMEM_BYTES);
    cudaFuncSetAttribute((const void*)gemm_kernel<1, false>,
                         cudaFuncAttributeMaxDynamicSharedMemorySize, SMEM_BYTES);
    cudaFuncSetAttribute((const void*)gemm_kernel<1, true>,
                         cudaFuncAttributeMaxDynamicSharedMemorySize, SMEM_BYTES);
    cudaFuncSetAttribute((const void*)gemm_kernel<2, false>,
                         cudaFuncAttributeMaxDynamicSharedMemorySize, SMEM_BYTES);

    // 1: gating  2: selection (exact fp32)
    gating_kernel<<<TT, 256>>>(x, gw, eb);
    select_kernel<<<EE, 1024>>>();

    // 3: x -> fp16
    roundx_kernel<<<TT * DD / 4 / 256, 256>>>(x);

    // 4,5: weight transpose-convert
    convT_kernel<<<dim3(2 * FF / 64, DD / 64, 1 + EE), 256>>>(
        sw1, rw1, sw1T, rw1T, DD, 2 * FF);
    convT_kernel<<<dim3(DD / 64, FF / 64, 1 + EE), 256>>>(
        sw2, rw2, sw2T, rw2T, FF, DD);

    // 6: shared GEMM1 (fused SwiGLU)
    gemm_kernel<1, false><<<dim3(16, 64, 1), 128, SMEM_BYTES>>>(
        Xr, sw1T, Hs, DD, 0, 0, 0, nullptr, nullptr, 0, nullptr, 0);
    // 7: shared GEMM2 (dense store)
    gemm_kernel<0, false><<<dim3(16, 64, 1), 128, SMEM_BYTES>>>(
        Hs, sw2T, out, FF, 0, 0, 0, nullptr, nullptr, 0, nullptr, 0);

    // 8: routed GEMM1 (gathered A, fused SwiGLU)
    gemm_kernel<1, true><<<dim3(16, MPAD / 128, EE), 128, SMEM_BYTES>>>(
        Xr, rw1T, Hs, DD,
        0, (size_t)2 * FF * DD, (size_t)MPAD * FF,
        nullptr, nullptr, 0, seltok, CAPX);
    // 9: routed GEMM2 (weighted scatter-add)
    gemm_kernel<2, false><<<dim3(16, MPAD / 128, EE), 128, SMEM_BYTES>>>(
        Hs, rw2T, out, FF,
        (size_t)MPAD * FF, (size_t)DD * FF, 0,
        seltok, selw, CAPX, nullptr, 0);
}